// round 15
// baseline (speedup 1.0000x reference)
#include <cuda_runtime.h>
#include <cuda_bf16.h>
#include <cstdint>

// Problem-size upper bounds (fixed by the dataset)
#define MAXE 500000
#define MAXN 100000
#define CC   128

// ---------------- scratch (device globals; no allocation) ----------------
__device__ float g_hpre[(size_t)MAXE * CC];          // lvl1 pre-BN (scatter input)
__device__ float g_epre[(size_t)MAXE * CC];          // edge MLP2 out pre-BN
__device__ float g_hidden[(size_t)MAXE * 2 * CC];    // edge MLP hidden
__device__ float g_hidden_n[(size_t)MAXN * 2 * CC];  // node MLP hidden
__device__ float g_lvl[(size_t)MAXN * CC];           // lvl_aggr [N,128]
__device__ float g_outpre_n[(size_t)MAXN * CC];      // node out pre-BN
__device__ float g_stat_sum[5 * 256];
__device__ float g_stat_sq[5 * 256];
__device__ float g_aff_a[5 * 256];
__device__ float g_aff_d[5 * 256];

__device__ __forceinline__ uint32_t f2tf32(float x) {
    uint32_t r;
    asm("cvt.rna.tf32.f32 %0, %1;" : "=r"(r) : "f"(x));
    return r;
}

// ---------------- scatter: lvl_aggr[s] += h, lvl_aggr[t] += h ----------------
__global__ void k_scatter(const int* __restrict__ ep, int E)
{
    int idx = blockIdx.x * blockDim.x + threadIdx.x;
    int total = E * 32;
    if (idx >= total) return;
    int e = idx >> 5;
    int c4 = (idx & 31) * 4;
    float4 v = *(const float4*)(g_hpre + (size_t)e * CC + c4);
    float4 a = *(const float4*)(g_aff_a + c4);
    float4 d = *(const float4*)(g_aff_d + c4);
    v.x = fmaxf(fmaf(a.x, v.x, d.x), 0.f);
    v.y = fmaxf(fmaf(a.y, v.y, d.y), 0.f);
    v.z = fmaxf(fmaf(a.z, v.z, d.z), 0.f);
    v.w = fmaxf(fmaf(a.w, v.w, d.w), 0.f);
    int s = ep[e];
    int t = ep[E + e];
    float* ps = g_lvl + (size_t)s * CC + c4;
    float* pt = g_lvl + (size_t)t * CC + c4;
    asm volatile("red.global.add.v4.f32 [%0], {%1,%2,%3,%4};"
                 :: "l"(ps), "f"(v.x), "f"(v.y), "f"(v.z), "f"(v.w) : "memory");
    asm volatile("red.global.add.v4.f32 [%0], {%1,%2,%3,%4};"
                 :: "l"(pt), "f"(v.x), "f"(v.y), "f"(v.z), "f"(v.w) : "memory");
}

// ---------------- fused tf32 tensor-core GEMM + BN-stats epilogue ----------------
// Round-14 math in a 4-independent-CTA shape: block tile 64x128, 256 threads
// (8 warps as 2m x 4n, warp tile 32x32), BK=16, double-buffered smem,
// lookahead-1 prefetch, shfl-reduced stats, templated MODE/K.
// __launch_bounds__(256,4): 256thr x 64regs x 4 CTAs = 65536 regs -> four
// INDEPENDENT barrier domains per SM so one CTA's per-iteration barrier stall
// is covered by the other three (R10/R11 showed independence, not warp count,
// is the binding resource).
// Per-element math identical to rounds 9/13/14 -> same rel_err.
// MODE 0: A = concat(node[s]+node[t], edge[row])     (K=256, gathers)
// MODE 1: A = (1+*eps)*A0[row] + A1[row]             (K=128)
// MODE 2: A = relu(aIn[k]*A0[row,k] + dIn[k])        (row stride K)
// MODE 3: A = (1+*eps)*edge[row] + node[s]+node[t]   (K=128, gathers)
#define BM 64
#define BN 128
#define BK 16
#define TPG 256

template<int MODE, int KV>
__global__ __launch_bounds__(TPG, 4) void k_gemm(
    const float* __restrict__ A0, const float* __restrict__ A1,
    const float* __restrict__ W,  const float* __restrict__ eps_ptr,
    const float* __restrict__ aIn, const float* __restrict__ dIn,
    const int* __restrict__ ep, int E,
    float* __restrict__ out, float* __restrict__ statSum, float* __restrict__ statSq,
    int M, int NC)
{
    __shared__ uint32_t As[2][BM][BK + 4];   // 10.2 KB
    __shared__ uint32_t Bs[2][BK][BN + 8];   // 17.4 KB
    __shared__ float ssum[BN];
    __shared__ float ssq[BN];

    const int tid    = threadIdx.x;
    const int warpId = tid >> 5;             // 0..7
    const int lane   = tid & 31;
    const int g      = lane >> 2;
    const int t      = lane & 3;
    const int m0w    = (warpId >> 2) * 32;   // 0 or 32
    const int n0w    = (warpId & 3) * 32;    // 0,32,64,96
    const int m_blk  = blockIdx.x * BM;
    const int nb     = blockIdx.y * BN;

    // A-loader geometry: 256 threads cover 64x16 in one float4 each
    const int aRowL = tid >> 2;              // 0..63
    const int k4    = (tid & 3) * 4;         // 0,4,8,12
    const int aRowG = m_blk + aRowL;
    int sIdx = 0, tIdx = 0;
    if constexpr (MODE == 0 || MODE == 3) {
        if (aRowG < M) {
            sIdx = ep[aRowG];
            tIdx = ep[E + aRowG];
        }
    }
    // B-loader geometry: 2 float4 per thread covering 16x128
    int bRowL[2], bColL[2];
#pragma unroll
    for (int j = 0; j < 2; j++) {
        int f = tid + j * 256;
        bRowL[j] = f >> 5;                   // 0..15
        bColL[j] = (f & 31) * 4;             // 0..124
    }

    float epsv = 0.f;
    if constexpr (MODE == 1 || MODE == 3) epsv = 1.f + __ldg(eps_ptr);

    float acc[2][4][4];
#pragma unroll
    for (int i = 0; i < 2; i++)
#pragma unroll
        for (int j = 0; j < 4; j++)
#pragma unroll
            for (int c = 0; c < 4; c++) acc[i][j][c] = 0.f;

    constexpr int nIter = KV / BK;           // 8 or 16, compile-time
    float4 aPre;
    float4 bPre[2];

    auto loadTile = [&](int it) {
        float4 av = make_float4(0.f, 0.f, 0.f, 0.f);
        if (aRowG < M) {
            int gk = it * BK + k4;
            if constexpr (MODE == 0) {
                if (gk < 128) {
                    float4 x = *(const float4*)(A0 + (size_t)sIdx * 128 + gk);
                    float4 y = *(const float4*)(A0 + (size_t)tIdx * 128 + gk);
                    av.x = x.x + y.x; av.y = x.y + y.y;
                    av.z = x.z + y.z; av.w = x.w + y.w;
                } else {
                    av = *(const float4*)(A1 + (size_t)aRowG * 128 + (gk - 128));
                }
            } else if constexpr (MODE == 1) {
                float4 x = *(const float4*)(A0 + (size_t)aRowG * 128 + gk);
                float4 y = *(const float4*)(A1 + (size_t)aRowG * 128 + gk);
                av.x = fmaf(epsv, x.x, y.x);
                av.y = fmaf(epsv, x.y, y.y);
                av.z = fmaf(epsv, x.z, y.z);
                av.w = fmaf(epsv, x.w, y.w);
            } else if constexpr (MODE == 2) {
                float4 x = *(const float4*)(A0 + (size_t)aRowG * KV + gk);
                float4 a = *(const float4*)(aIn + gk);
                float4 d = *(const float4*)(dIn + gk);
                av.x = fmaxf(fmaf(a.x, x.x, d.x), 0.f);
                av.y = fmaxf(fmaf(a.y, x.y, d.y), 0.f);
                av.z = fmaxf(fmaf(a.z, x.z, d.z), 0.f);
                av.w = fmaxf(fmaf(a.w, x.w, d.w), 0.f);
            } else { // MODE 3
                float4 eV = *(const float4*)(A0 + (size_t)aRowG * 128 + gk);
                float4 x = *(const float4*)(A1 + (size_t)sIdx * 128 + gk);
                float4 y = *(const float4*)(A1 + (size_t)tIdx * 128 + gk);
                av.x = fmaf(epsv, eV.x, x.x + y.x);
                av.y = fmaf(epsv, eV.y, x.y + y.y);
                av.z = fmaf(epsv, eV.z, x.z + y.z);
                av.w = fmaf(epsv, eV.w, x.w + y.w);
            }
        }
        aPre = av;
#pragma unroll
        for (int j = 0; j < 2; j++)
            bPre[j] = *(const float4*)(W + (size_t)(it * BK + bRowL[j]) * NC + nb + bColL[j]);
    };
    auto storeTile = [&](int buf) {
        *(uint4*)&As[buf][aRowL][k4] =
            make_uint4(f2tf32(aPre.x), f2tf32(aPre.y), f2tf32(aPre.z), f2tf32(aPre.w));
#pragma unroll
        for (int j = 0; j < 2; j++)
            *(uint4*)&Bs[buf][bRowL[j]][bColL[j]] =
                make_uint4(f2tf32(bPre[j].x), f2tf32(bPre[j].y),
                           f2tf32(bPre[j].z), f2tf32(bPre[j].w));
    };
    auto iterBody = [&](int it) {
        const int buf = it & 1;
        if (it + 1 < nIter) loadTile(it + 1);   // overlap with MMAs below

#pragma unroll
        for (int ks = 0; ks < 2; ks++) {
            const int kb = ks * 8;
            uint32_t af[2][4];
            uint32_t bf[4][2];
#pragma unroll
            for (int mt = 0; mt < 2; mt++) {
                int r = m0w + mt * 16 + g;
                af[mt][0] = As[buf][r][kb + t];
                af[mt][1] = As[buf][r + 8][kb + t];
                af[mt][2] = As[buf][r][kb + t + 4];
                af[mt][3] = As[buf][r + 8][kb + t + 4];
            }
#pragma unroll
            for (int nt = 0; nt < 4; nt++) {
                int c = n0w + nt * 8 + g;
                bf[nt][0] = Bs[buf][kb + t][c];
                bf[nt][1] = Bs[buf][kb + t + 4][c];
            }
#pragma unroll
            for (int mt = 0; mt < 2; mt++)
#pragma unroll
                for (int nt = 0; nt < 4; nt++) {
                    asm volatile(
                        "mma.sync.aligned.m16n8k8.row.col.f32.tf32.tf32.f32 "
                        "{%0,%1,%2,%3}, {%4,%5,%6,%7}, {%8,%9}, {%0,%1,%2,%3};"
                        : "+f"(acc[mt][nt][0]), "+f"(acc[mt][nt][1]),
                          "+f"(acc[mt][nt][2]), "+f"(acc[mt][nt][3])
                        : "r"(af[mt][0]), "r"(af[mt][1]), "r"(af[mt][2]), "r"(af[mt][3]),
                          "r"(bf[nt][0]), "r"(bf[nt][1]));
                }
        }

        if (it + 1 < nIter) storeTile(buf ^ 1);
        __syncthreads();
    };

    loadTile(0);
    storeTile(0);
    __syncthreads();

    if constexpr (nIter == 8) {
#pragma unroll
        for (int it = 0; it < nIter; it++) iterBody(it);
    } else {
#pragma unroll 4
        for (int it = 0; it < nIter; it++) iterBody(it);
    }

    // ---- epilogue: per-column stats (shfl-reduced) + store ----
    for (int i = tid; i < BN; i += TPG) { ssum[i] = 0.f; ssq[i] = 0.f; }
    __syncthreads();

#pragma unroll
    for (int nt = 0; nt < 4; nt++) {
        float se = 0.f, qe = 0.f, so = 0.f, qo = 0.f;
#pragma unroll
        for (int mt = 0; mt < 2; mt++) {
            float c0 = acc[mt][nt][0], c1 = acc[mt][nt][1];
            float c2 = acc[mt][nt][2], c3 = acc[mt][nt][3];
            se += c0 + c2; qe += c0 * c0 + c2 * c2;
            so += c1 + c3; qo += c1 * c1 + c3 * c3;
        }
        // butterfly-sum across the 8 g-lanes (same t, lanes stride 4)
#pragma unroll
        for (int off = 16; off >= 4; off >>= 1) {
            se += __shfl_xor_sync(0xffffffffu, se, off);
            qe += __shfl_xor_sync(0xffffffffu, qe, off);
            so += __shfl_xor_sync(0xffffffffu, so, off);
            qo += __shfl_xor_sync(0xffffffffu, qo, off);
        }
        if (g == 0) {
            int ce = n0w + nt * 8 + 2 * t;
            atomicAdd(&ssum[ce], se);     atomicAdd(&ssq[ce], qe);
            atomicAdd(&ssum[ce + 1], so); atomicAdd(&ssq[ce + 1], qo);
        }
    }

#pragma unroll
    for (int mt = 0; mt < 2; mt++) {
        int r0 = m_blk + m0w + mt * 16 + g;
        int r1 = r0 + 8;
#pragma unroll
        for (int nt = 0; nt < 4; nt++) {
            int ce = n0w + nt * 8 + 2 * t;
            if (r0 < M) {
                float2 v = make_float2(acc[mt][nt][0], acc[mt][nt][1]);
                *(float2*)(out + (size_t)r0 * NC + nb + ce) = v;
            }
            if (r1 < M) {
                float2 v = make_float2(acc[mt][nt][2], acc[mt][nt][3]);
                *(float2*)(out + (size_t)r1 * NC + nb + ce) = v;
            }
        }
    }

    __syncthreads();
    for (int i = tid; i < BN; i += TPG) {
        atomicAdd(&statSum[nb + i], ssum[i]);
        atomicAdd(&statSq[nb + i], ssq[i]);
    }
}

// ---------------- finalize BN stats -> affine (a, d) ----------------
__global__ void k_finalize(const float* __restrict__ sums, const float* __restrict__ sqs,
                           const float* __restrict__ g, const float* __restrict__ b,
                           float* __restrict__ aA, float* __restrict__ aD,
                           int ncols, float invM)
{
    int i = blockIdx.x * blockDim.x + threadIdx.x;
    if (i >= ncols) return;
    float mu = sums[i] * invM;
    float var = sqs[i] * invM - mu * mu;
    float rs = rsqrtf(var + 1e-5f);
    float a = g[i] * rs;
    aA[i] = a;
    aD[i] = fmaf(-mu, a, b[i]);
}

// ---------------- final normalize + ReLU -> d_out ----------------
__global__ void k_norm(const float* __restrict__ in,
                       const float* __restrict__ aA, const float* __restrict__ aD,
                       float* __restrict__ out, int M)
{
    int idx = blockIdx.x * blockDim.x + threadIdx.x;
    int total = M * 32;
    if (idx >= total) return;
    int c4 = (idx & 31) * 4;
    float4 v = ((const float4*)in)[idx];
    float4 a = *(const float4*)(aA + c4);
    float4 d = *(const float4*)(aD + c4);
    v.x = fmaxf(fmaf(a.x, v.x, d.x), 0.f);
    v.y = fmaxf(fmaf(a.y, v.y, d.y), 0.f);
    v.z = fmaxf(fmaf(a.z, v.z, d.z), 0.f);
    v.w = fmaxf(fmaf(a.w, v.w, d.w), 0.f);
    ((float4*)out)[idx] = v;
}

// ---------------- host launch ----------------
extern "C" void kernel_launch(void* const* d_in, const int* in_sizes, int n_in,
                              void* d_out, int out_size)
{
    const float* node   = (const float*)d_in[0];
    const float* edge   = (const float*)d_in[1];
    const int*   ep     = (const int*)  d_in[2];
    const float* W_lvl1 = (const float*)d_in[3];
    const float* gl1    = (const float*)d_in[4];
    const float* bl1    = (const float*)d_in[5];
    const float* W_n1   = (const float*)d_in[6];
    const float* gn1    = (const float*)d_in[7];
    const float* bn1    = (const float*)d_in[8];
    const float* W_n2   = (const float*)d_in[9];
    const float* gn2    = (const float*)d_in[10];
    const float* bn2    = (const float*)d_in[11];
    const float* W_e1   = (const float*)d_in[12];
    const float* ge1    = (const float*)d_in[13];
    const float* be1    = (const float*)d_in[14];
    const float* W_e2   = (const float*)d_in[15];
    const float* ge2    = (const float*)d_in[16];
    const float* be2    = (const float*)d_in[17];
    const float* eps1   = (const float*)d_in[18];
    const float* eps2   = (const float*)d_in[19];
    float* outp = (float*)d_out;

    const int Cc = in_sizes[4];                  // 128
    const int Nn = in_sizes[0] / Cc;
    const int Ee = in_sizes[1] / Cc;

    float *hpre, *epre, *hidden, *hidden_n, *lvl, *outpre_n, *ssum, *ssq, *affA, *affD;
    cudaGetSymbolAddress((void**)&hpre,     g_hpre);
    cudaGetSymbolAddress((void**)&epre,     g_epre);
    cudaGetSymbolAddress((void**)&hidden,   g_hidden);
    cudaGetSymbolAddress((void**)&hidden_n, g_hidden_n);
    cudaGetSymbolAddress((void**)&lvl,      g_lvl);
    cudaGetSymbolAddress((void**)&outpre_n, g_outpre_n);
    cudaGetSymbolAddress((void**)&ssum,     g_stat_sum);
    cudaGetSymbolAddress((void**)&ssq,      g_stat_sq);
    cudaGetSymbolAddress((void**)&affA,     g_aff_a);
    cudaGetSymbolAddress((void**)&affD,     g_aff_d);

    static bool initDone = false;
    static cudaStream_t s1 = nullptr;
    static cudaEvent_t evFork = nullptr, evJoin = nullptr;
    if (!initDone) {
        cudaStreamCreateWithFlags(&s1, cudaStreamNonBlocking);
        cudaEventCreateWithFlags(&evFork, cudaEventDisableTiming);
        cudaEventCreateWithFlags(&evJoin, cudaEventDisableTiming);
        initDone = true;
    }

    cudaMemsetAsync(lvl,  0, (size_t)Nn * Cc * sizeof(float), 0);
    cudaMemsetAsync(ssum, 0, 5 * 256 * sizeof(float), 0);
    cudaMemsetAsync(ssq,  0, 5 * 256 * sizeof(float), 0);

    const int TPB = 256;
    const int eThreads = Ee * 32;
    const int nThreads = Nn * 32;
    const int gxE = (Ee + BM - 1) / BM;
    const int gxN = (Nn + BM - 1) / BM;

    // fork: edge chain on s1, node chain on stream 0
    cudaEventRecord(evFork, 0);
    cudaStreamWaitEvent(s1, evFork, 0);

    // ===== stream 0: lvl1 -> scatter -> node MLP =====
    k_gemm<0, 256><<<dim3(gxE, 1), TPG, 0, 0>>>(node, edge, W_lvl1, nullptr, nullptr, nullptr,
                                                ep, Ee,
                                                hpre, ssum + 0, ssq + 0, Ee, 128);
    k_finalize<<<1, 256, 0, 0>>>(ssum + 0, ssq + 0, gl1, bl1, affA + 0, affD + 0,
                                 128, 1.f / (float)Ee);
    k_scatter<<<(eThreads + TPB - 1) / TPB, TPB, 0, 0>>>(ep, Ee);

    k_gemm<1, 128><<<dim3(gxN, 2), TPG, 0, 0>>>(node, lvl, W_n1, eps1, nullptr, nullptr,
                                                nullptr, 0,
                                                hidden_n, ssum + 256, ssq + 256, Nn, 256);
    k_finalize<<<1, 256, 0, 0>>>(ssum + 256, ssq + 256, gn1, bn1, affA + 256, affD + 256,
                                 256, 1.f / (float)Nn);
    k_gemm<2, 256><<<dim3(gxN, 1), TPG, 0, 0>>>(hidden_n, nullptr, W_n2, nullptr,
                                                affA + 256, affD + 256, nullptr, 0,
                                                outpre_n, ssum + 512, ssq + 512, Nn, 128);
    k_finalize<<<1, 256, 0, 0>>>(ssum + 512, ssq + 512, gn2, bn2, affA + 512, affD + 512,
                                 128, 1.f / (float)Nn);
    k_norm<<<(nThreads + TPB - 1) / TPB, TPB, 0, 0>>>(outpre_n, affA + 512, affD + 512,
                                                      outp, Nn);

    // ===== stream s1: edge MLP =====
    k_gemm<3, 128><<<dim3(gxE, 2), TPG, 0, s1>>>(edge, node, W_e1, eps2, nullptr, nullptr,
                                                 ep, Ee,
                                                 hidden, ssum + 768, ssq + 768, Ee, 256);
    k_finalize<<<1, 256, 0, s1>>>(ssum + 768, ssq + 768, ge1, be1, affA + 768, affD + 768,
                                  256, 1.f / (float)Ee);
    k_gemm<2, 256><<<dim3(gxE, 1), TPG, 0, s1>>>(hidden, nullptr, W_e2, nullptr,
                                                 affA + 768, affD + 768, nullptr, 0,
                                                 epre, ssum + 1024, ssq + 1024, Ee, 128);
    k_finalize<<<1, 256, 0, s1>>>(ssum + 1024, ssq + 1024, ge2, be2, affA + 1024, affD + 1024,
                                  128, 1.f / (float)Ee);
    k_norm<<<(eThreads + TPB - 1) / TPB, TPB, 0, s1>>>(epre, affA + 1024, affD + 1024,
                                                       outp + (size_t)Nn * Cc, Ee);

    // join
    cudaEventRecord(evJoin, s1);
    cudaStreamWaitEvent(0, evJoin, 0);
}

// round 16
// speedup vs baseline: 1.0338x; 1.0338x over previous
#include <cuda_runtime.h>
#include <cuda_bf16.h>
#include <cstdint>

// Problem-size upper bounds (fixed by the dataset)
#define MAXE 500000
#define MAXN 100000
#define CC   128

// ---------------- scratch (device globals; no allocation) ----------------
__device__ float g_hpre[(size_t)MAXE * CC];          // lvl1 pre-BN (scatter input)
__device__ float g_epre[(size_t)MAXE * CC];          // edge MLP2 out pre-BN
__device__ float g_hidden[(size_t)MAXE * 2 * CC];    // edge MLP hidden
__device__ float g_hidden_n[(size_t)MAXN * 2 * CC];  // node MLP hidden
__device__ float g_lvl[(size_t)MAXN * CC];           // lvl_aggr [N,128]
__device__ float g_outpre_n[(size_t)MAXN * CC];      // node out pre-BN
__device__ float g_stat_sum[5 * 256];
__device__ float g_stat_sq[5 * 256];
__device__ float g_aff_a[5 * 256];
__device__ float g_aff_d[5 * 256];

__device__ __forceinline__ uint32_t f2tf32(float x) {
    uint32_t r;
    asm("cvt.rna.tf32.f32 %0, %1;" : "=r"(r) : "f"(x));
    return r;
}

// ---------------- scatter: lvl_aggr[s] += h, lvl_aggr[t] += h ----------------
__global__ void k_scatter(const int* __restrict__ ep, int E)
{
    int idx = blockIdx.x * blockDim.x + threadIdx.x;
    int total = E * 32;
    if (idx >= total) return;
    int e = idx >> 5;
    int c4 = (idx & 31) * 4;
    float4 v = *(const float4*)(g_hpre + (size_t)e * CC + c4);
    float4 a = *(const float4*)(g_aff_a + c4);
    float4 d = *(const float4*)(g_aff_d + c4);
    v.x = fmaxf(fmaf(a.x, v.x, d.x), 0.f);
    v.y = fmaxf(fmaf(a.y, v.y, d.y), 0.f);
    v.z = fmaxf(fmaf(a.z, v.z, d.z), 0.f);
    v.w = fmaxf(fmaf(a.w, v.w, d.w), 0.f);
    int s = ep[e];
    int t = ep[E + e];
    float* ps = g_lvl + (size_t)s * CC + c4;
    float* pt = g_lvl + (size_t)t * CC + c4;
    asm volatile("red.global.add.v4.f32 [%0], {%1,%2,%3,%4};"
                 :: "l"(ps), "f"(v.x), "f"(v.y), "f"(v.z), "f"(v.w) : "memory");
    asm volatile("red.global.add.v4.f32 [%0], {%1,%2,%3,%4};"
                 :: "l"(pt), "f"(v.x), "f"(v.y), "f"(v.z), "f"(v.w) : "memory");
}

// ---------------- fused tf32 tensor-core GEMM + BN-stats epilogue ----------------
// Round-15 skeleton (block tile 64x128, 256 threads, 2m x 4n warps of 32x32,
// BK=16, double-buffered smem, lookahead-1 prefetch, shfl stats, 4 CTAs/SM).
// ONE change vs round 15: grid mapping swapped — N-slab is blockIdx.x (fast),
// M-tile is blockIdx.y — so consecutively-scheduled blocks share the same A
// rows and the second N-slab of NC=256 GEMMs hits L2 instead of re-reading
// the A panel from DRAM.
// MODE 0: A = concat(node[s]+node[t], edge[row])     (K=256, gathers)
// MODE 1: A = (1+*eps)*A0[row] + A1[row]             (K=128)
// MODE 2: A = relu(aIn[k]*A0[row,k] + dIn[k])        (row stride K)
// MODE 3: A = (1+*eps)*edge[row] + node[s]+node[t]   (K=128, gathers)
#define BM 64
#define BN 128
#define BK 16
#define TPG 256

template<int MODE, int KV>
__global__ __launch_bounds__(TPG, 4) void k_gemm(
    const float* __restrict__ A0, const float* __restrict__ A1,
    const float* __restrict__ W,  const float* __restrict__ eps_ptr,
    const float* __restrict__ aIn, const float* __restrict__ dIn,
    const int* __restrict__ ep, int E,
    float* __restrict__ out, float* __restrict__ statSum, float* __restrict__ statSq,
    int M, int NC)
{
    __shared__ uint32_t As[2][BM][BK + 4];   // 10.2 KB
    __shared__ uint32_t Bs[2][BK][BN + 8];   // 17.4 KB
    __shared__ float ssum[BN];
    __shared__ float ssq[BN];

    const int tid    = threadIdx.x;
    const int warpId = tid >> 5;             // 0..7
    const int lane   = tid & 31;
    const int g      = lane >> 2;
    const int t      = lane & 3;
    const int m0w    = (warpId >> 2) * 32;   // 0 or 32
    const int n0w    = (warpId & 3) * 32;    // 0,32,64,96
    const int m_blk  = blockIdx.y * BM;      // M on slow axis
    const int nb     = blockIdx.x * BN;      // N on fast axis (A-tile reuse in L2)

    // A-loader geometry: 256 threads cover 64x16 in one float4 each
    const int aRowL = tid >> 2;              // 0..63
    const int k4    = (tid & 3) * 4;         // 0,4,8,12
    const int aRowG = m_blk + aRowL;
    int sIdx = 0, tIdx = 0;
    if constexpr (MODE == 0 || MODE == 3) {
        if (aRowG < M) {
            sIdx = ep[aRowG];
            tIdx = ep[E + aRowG];
        }
    }
    // B-loader geometry: 2 float4 per thread covering 16x128
    int bRowL[2], bColL[2];
#pragma unroll
    for (int j = 0; j < 2; j++) {
        int f = tid + j * 256;
        bRowL[j] = f >> 5;                   // 0..15
        bColL[j] = (f & 31) * 4;             // 0..124
    }

    float epsv = 0.f;
    if constexpr (MODE == 1 || MODE == 3) epsv = 1.f + __ldg(eps_ptr);

    float acc[2][4][4];
#pragma unroll
    for (int i = 0; i < 2; i++)
#pragma unroll
        for (int j = 0; j < 4; j++)
#pragma unroll
            for (int c = 0; c < 4; c++) acc[i][j][c] = 0.f;

    constexpr int nIter = KV / BK;           // 8 or 16, compile-time
    float4 aPre;
    float4 bPre[2];

    auto loadTile = [&](int it) {
        float4 av = make_float4(0.f, 0.f, 0.f, 0.f);
        if (aRowG < M) {
            int gk = it * BK + k4;
            if constexpr (MODE == 0) {
                if (gk < 128) {
                    float4 x = *(const float4*)(A0 + (size_t)sIdx * 128 + gk);
                    float4 y = *(const float4*)(A0 + (size_t)tIdx * 128 + gk);
                    av.x = x.x + y.x; av.y = x.y + y.y;
                    av.z = x.z + y.z; av.w = x.w + y.w;
                } else {
                    av = *(const float4*)(A1 + (size_t)aRowG * 128 + (gk - 128));
                }
            } else if constexpr (MODE == 1) {
                float4 x = *(const float4*)(A0 + (size_t)aRowG * 128 + gk);
                float4 y = *(const float4*)(A1 + (size_t)aRowG * 128 + gk);
                av.x = fmaf(epsv, x.x, y.x);
                av.y = fmaf(epsv, x.y, y.y);
                av.z = fmaf(epsv, x.z, y.z);
                av.w = fmaf(epsv, x.w, y.w);
            } else if constexpr (MODE == 2) {
                float4 x = *(const float4*)(A0 + (size_t)aRowG * KV + gk);
                float4 a = *(const float4*)(aIn + gk);
                float4 d = *(const float4*)(dIn + gk);
                av.x = fmaxf(fmaf(a.x, x.x, d.x), 0.f);
                av.y = fmaxf(fmaf(a.y, x.y, d.y), 0.f);
                av.z = fmaxf(fmaf(a.z, x.z, d.z), 0.f);
                av.w = fmaxf(fmaf(a.w, x.w, d.w), 0.f);
            } else { // MODE 3
                float4 eV = *(const float4*)(A0 + (size_t)aRowG * 128 + gk);
                float4 x = *(const float4*)(A1 + (size_t)sIdx * 128 + gk);
                float4 y = *(const float4*)(A1 + (size_t)tIdx * 128 + gk);
                av.x = fmaf(epsv, eV.x, x.x + y.x);
                av.y = fmaf(epsv, eV.y, x.y + y.y);
                av.z = fmaf(epsv, eV.z, x.z + y.z);
                av.w = fmaf(epsv, eV.w, x.w + y.w);
            }
        }
        aPre = av;
#pragma unroll
        for (int j = 0; j < 2; j++)
            bPre[j] = *(const float4*)(W + (size_t)(it * BK + bRowL[j]) * NC + nb + bColL[j]);
    };
    auto storeTile = [&](int buf) {
        *(uint4*)&As[buf][aRowL][k4] =
            make_uint4(f2tf32(aPre.x), f2tf32(aPre.y), f2tf32(aPre.z), f2tf32(aPre.w));
#pragma unroll
        for (int j = 0; j < 2; j++)
            *(uint4*)&Bs[buf][bRowL[j]][bColL[j]] =
                make_uint4(f2tf32(bPre[j].x), f2tf32(bPre[j].y),
                           f2tf32(bPre[j].z), f2tf32(bPre[j].w));
    };
    auto iterBody = [&](int it) {
        const int buf = it & 1;
        if (it + 1 < nIter) loadTile(it + 1);   // overlap with MMAs below

#pragma unroll
        for (int ks = 0; ks < 2; ks++) {
            const int kb = ks * 8;
            uint32_t af[2][4];
            uint32_t bf[4][2];
#pragma unroll
            for (int mt = 0; mt < 2; mt++) {
                int r = m0w + mt * 16 + g;
                af[mt][0] = As[buf][r][kb + t];
                af[mt][1] = As[buf][r + 8][kb + t];
                af[mt][2] = As[buf][r][kb + t + 4];
                af[mt][3] = As[buf][r + 8][kb + t + 4];
            }
#pragma unroll
            for (int nt = 0; nt < 4; nt++) {
                int c = n0w + nt * 8 + g;
                bf[nt][0] = Bs[buf][kb + t][c];
                bf[nt][1] = Bs[buf][kb + t + 4][c];
            }
#pragma unroll
            for (int mt = 0; mt < 2; mt++)
#pragma unroll
                for (int nt = 0; nt < 4; nt++) {
                    asm volatile(
                        "mma.sync.aligned.m16n8k8.row.col.f32.tf32.tf32.f32 "
                        "{%0,%1,%2,%3}, {%4,%5,%6,%7}, {%8,%9}, {%0,%1,%2,%3};"
                        : "+f"(acc[mt][nt][0]), "+f"(acc[mt][nt][1]),
                          "+f"(acc[mt][nt][2]), "+f"(acc[mt][nt][3])
                        : "r"(af[mt][0]), "r"(af[mt][1]), "r"(af[mt][2]), "r"(af[mt][3]),
                          "r"(bf[nt][0]), "r"(bf[nt][1]));
                }
        }

        if (it + 1 < nIter) storeTile(buf ^ 1);
        __syncthreads();
    };

    loadTile(0);
    storeTile(0);
    __syncthreads();

    if constexpr (nIter == 8) {
#pragma unroll
        for (int it = 0; it < nIter; it++) iterBody(it);
    } else {
#pragma unroll 4
        for (int it = 0; it < nIter; it++) iterBody(it);
    }

    // ---- epilogue: per-column stats (shfl-reduced) + store ----
    for (int i = tid; i < BN; i += TPG) { ssum[i] = 0.f; ssq[i] = 0.f; }
    __syncthreads();

#pragma unroll
    for (int nt = 0; nt < 4; nt++) {
        float se = 0.f, qe = 0.f, so = 0.f, qo = 0.f;
#pragma unroll
        for (int mt = 0; mt < 2; mt++) {
            float c0 = acc[mt][nt][0], c1 = acc[mt][nt][1];
            float c2 = acc[mt][nt][2], c3 = acc[mt][nt][3];
            se += c0 + c2; qe += c0 * c0 + c2 * c2;
            so += c1 + c3; qo += c1 * c1 + c3 * c3;
        }
        // butterfly-sum across the 8 g-lanes (same t, lanes stride 4)
#pragma unroll
        for (int off = 16; off >= 4; off >>= 1) {
            se += __shfl_xor_sync(0xffffffffu, se, off);
            qe += __shfl_xor_sync(0xffffffffu, qe, off);
            so += __shfl_xor_sync(0xffffffffu, so, off);
            qo += __shfl_xor_sync(0xffffffffu, qo, off);
        }
        if (g == 0) {
            int ce = n0w + nt * 8 + 2 * t;
            atomicAdd(&ssum[ce], se);     atomicAdd(&ssq[ce], qe);
            atomicAdd(&ssum[ce + 1], so); atomicAdd(&ssq[ce + 1], qo);
        }
    }

#pragma unroll
    for (int mt = 0; mt < 2; mt++) {
        int r0 = m_blk + m0w + mt * 16 + g;
        int r1 = r0 + 8;
#pragma unroll
        for (int nt = 0; nt < 4; nt++) {
            int ce = n0w + nt * 8 + 2 * t;
            if (r0 < M) {
                float2 v = make_float2(acc[mt][nt][0], acc[mt][nt][1]);
                *(float2*)(out + (size_t)r0 * NC + nb + ce) = v;
            }
            if (r1 < M) {
                float2 v = make_float2(acc[mt][nt][2], acc[mt][nt][3]);
                *(float2*)(out + (size_t)r1 * NC + nb + ce) = v;
            }
        }
    }

    __syncthreads();
    for (int i = tid; i < BN; i += TPG) {
        atomicAdd(&statSum[nb + i], ssum[i]);
        atomicAdd(&statSq[nb + i], ssq[i]);
    }
}

// ---------------- finalize BN stats -> affine (a, d) ----------------
__global__ void k_finalize(const float* __restrict__ sums, const float* __restrict__ sqs,
                           const float* __restrict__ g, const float* __restrict__ b,
                           float* __restrict__ aA, float* __restrict__ aD,
                           int ncols, float invM)
{
    int i = blockIdx.x * blockDim.x + threadIdx.x;
    if (i >= ncols) return;
    float mu = sums[i] * invM;
    float var = sqs[i] * invM - mu * mu;
    float rs = rsqrtf(var + 1e-5f);
    float a = g[i] * rs;
    aA[i] = a;
    aD[i] = fmaf(-mu, a, b[i]);
}

// ---------------- final normalize + ReLU -> d_out ----------------
__global__ void k_norm(const float* __restrict__ in,
                       const float* __restrict__ aA, const float* __restrict__ aD,
                       float* __restrict__ out, int M)
{
    int idx = blockIdx.x * blockDim.x + threadIdx.x;
    int total = M * 32;
    if (idx >= total) return;
    int c4 = (idx & 31) * 4;
    float4 v = ((const float4*)in)[idx];
    float4 a = *(const float4*)(aA + c4);
    float4 d = *(const float4*)(aD + c4);
    v.x = fmaxf(fmaf(a.x, v.x, d.x), 0.f);
    v.y = fmaxf(fmaf(a.y, v.y, d.y), 0.f);
    v.z = fmaxf(fmaf(a.z, v.z, d.z), 0.f);
    v.w = fmaxf(fmaf(a.w, v.w, d.w), 0.f);
    ((float4*)out)[idx] = v;
}

// ---------------- host launch ----------------
extern "C" void kernel_launch(void* const* d_in, const int* in_sizes, int n_in,
                              void* d_out, int out_size)
{
    const float* node   = (const float*)d_in[0];
    const float* edge   = (const float*)d_in[1];
    const int*   ep     = (const int*)  d_in[2];
    const float* W_lvl1 = (const float*)d_in[3];
    const float* gl1    = (const float*)d_in[4];
    const float* bl1    = (const float*)d_in[5];
    const float* W_n1   = (const float*)d_in[6];
    const float* gn1    = (const float*)d_in[7];
    const float* bn1    = (const float*)d_in[8];
    const float* W_n2   = (const float*)d_in[9];
    const float* gn2    = (const float*)d_in[10];
    const float* bn2    = (const float*)d_in[11];
    const float* W_e1   = (const float*)d_in[12];
    const float* ge1    = (const float*)d_in[13];
    const float* be1    = (const float*)d_in[14];
    const float* W_e2   = (const float*)d_in[15];
    const float* ge2    = (const float*)d_in[16];
    const float* be2    = (const float*)d_in[17];
    const float* eps1   = (const float*)d_in[18];
    const float* eps2   = (const float*)d_in[19];
    float* outp = (float*)d_out;

    const int Cc = in_sizes[4];                  // 128
    const int Nn = in_sizes[0] / Cc;
    const int Ee = in_sizes[1] / Cc;

    float *hpre, *epre, *hidden, *hidden_n, *lvl, *outpre_n, *ssum, *ssq, *affA, *affD;
    cudaGetSymbolAddress((void**)&hpre,     g_hpre);
    cudaGetSymbolAddress((void**)&epre,     g_epre);
    cudaGetSymbolAddress((void**)&hidden,   g_hidden);
    cudaGetSymbolAddress((void**)&hidden_n, g_hidden_n);
    cudaGetSymbolAddress((void**)&lvl,      g_lvl);
    cudaGetSymbolAddress((void**)&outpre_n, g_outpre_n);
    cudaGetSymbolAddress((void**)&ssum,     g_stat_sum);
    cudaGetSymbolAddress((void**)&ssq,      g_stat_sq);
    cudaGetSymbolAddress((void**)&affA,     g_aff_a);
    cudaGetSymbolAddress((void**)&affD,     g_aff_d);

    static bool initDone = false;
    static cudaStream_t s1 = nullptr;
    static cudaEvent_t evFork = nullptr, evJoin = nullptr;
    if (!initDone) {
        cudaStreamCreateWithFlags(&s1, cudaStreamNonBlocking);
        cudaEventCreateWithFlags(&evFork, cudaEventDisableTiming);
        cudaEventCreateWithFlags(&evJoin, cudaEventDisableTiming);
        initDone = true;
    }

    cudaMemsetAsync(lvl,  0, (size_t)Nn * Cc * sizeof(float), 0);
    cudaMemsetAsync(ssum, 0, 5 * 256 * sizeof(float), 0);
    cudaMemsetAsync(ssq,  0, 5 * 256 * sizeof(float), 0);

    const int TPB = 256;
    const int eThreads = Ee * 32;
    const int nThreads = Nn * 32;
    const int gxE = (Ee + BM - 1) / BM;
    const int gxN = (Nn + BM - 1) / BM;

    // fork: edge chain on s1, node chain on stream 0
    cudaEventRecord(evFork, 0);
    cudaStreamWaitEvent(s1, evFork, 0);

    // ===== stream 0: lvl1 -> scatter -> node MLP =====
    // grid = (N-slabs, M-tiles): N fast so consecutive blocks reuse A rows
    k_gemm<0, 256><<<dim3(1, gxE), TPG, 0, 0>>>(node, edge, W_lvl1, nullptr, nullptr, nullptr,
                                                ep, Ee,
                                                hpre, ssum + 0, ssq + 0, Ee, 128);
    k_finalize<<<1, 256, 0, 0>>>(ssum + 0, ssq + 0, gl1, bl1, affA + 0, affD + 0,
                                 128, 1.f / (float)Ee);
    k_scatter<<<(eThreads + TPB - 1) / TPB, TPB, 0, 0>>>(ep, Ee);

    k_gemm<1, 128><<<dim3(2, gxN), TPG, 0, 0>>>(node, lvl, W_n1, eps1, nullptr, nullptr,
                                                nullptr, 0,
                                                hidden_n, ssum + 256, ssq + 256, Nn, 256);
    k_finalize<<<1, 256, 0, 0>>>(ssum + 256, ssq + 256, gn1, bn1, affA + 256, affD + 256,
                                 256, 1.f / (float)Nn);
    k_gemm<2, 256><<<dim3(1, gxN), TPG, 0, 0>>>(hidden_n, nullptr, W_n2, nullptr,
                                                affA + 256, affD + 256, nullptr, 0,
                                                outpre_n, ssum + 512, ssq + 512, Nn, 128);
    k_finalize<<<1, 256, 0, 0>>>(ssum + 512, ssq + 512, gn2, bn2, affA + 512, affD + 512,
                                 128, 1.f / (float)Nn);
    k_norm<<<(nThreads + TPB - 1) / TPB, TPB, 0, 0>>>(outpre_n, affA + 512, affD + 512,
                                                      outp, Nn);

    // ===== stream s1: edge MLP =====
    k_gemm<3, 128><<<dim3(2, gxE), TPG, 0, s1>>>(edge, node, W_e1, eps2, nullptr, nullptr,
                                                 ep, Ee,
                                                 hidden, ssum + 768, ssq + 768, Ee, 256);
    k_finalize<<<1, 256, 0, s1>>>(ssum + 768, ssq + 768, ge1, be1, affA + 768, affD + 768,
                                  256, 1.f / (float)Ee);
    k_gemm<2, 256><<<dim3(1, gxE), TPG, 0, s1>>>(hidden, nullptr, W_e2, nullptr,
                                                 affA + 768, affD + 768, nullptr, 0,
                                                 epre, ssum + 1024, ssq + 1024, Ee, 128);
    k_finalize<<<1, 256, 0, s1>>>(ssum + 1024, ssq + 1024, ge2, be2, affA + 1024, affD + 1024,
                                  128, 1.f / (float)Ee);
    k_norm<<<(eThreads + TPB - 1) / TPB, TPB, 0, s1>>>(epre, affA + 1024, affD + 1024,
                                                       outp + (size_t)Nn * Cc, Ee);

    // join
    cudaEventRecord(evJoin, s1);
    cudaStreamWaitEvent(0, evJoin, 0);
}

// round 17
// speedup vs baseline: 1.2350x; 1.1947x over previous
#include <cuda_runtime.h>
#include <cuda_bf16.h>
#include <cstdint>

// Problem-size upper bounds (fixed by the dataset)
#define MAXE 500000
#define MAXN 100000
#define CC   128

// ---------------- scratch (device globals; no allocation) ----------------
__device__ float g_hpre[(size_t)MAXE * CC];          // lvl1 pre-BN (scatter input)
__device__ float g_epre[(size_t)MAXE * CC];          // edge MLP2 out pre-BN
__device__ float g_hidden[(size_t)MAXE * 2 * CC];    // edge MLP hidden
__device__ float g_hidden_n[(size_t)MAXN * 2 * CC];  // node MLP hidden
__device__ float g_lvl[(size_t)MAXN * CC];           // lvl_aggr [N,128]
__device__ float g_outpre_n[(size_t)MAXN * CC];      // node out pre-BN
__device__ float g_stat_sum[5 * 256];
__device__ float g_stat_sq[5 * 256];
__device__ float g_aff_a[5 * 256];
__device__ float g_aff_d[5 * 256];

__device__ __forceinline__ uint32_t f2tf32(float x) {
    uint32_t r;
    asm("cvt.rna.tf32.f32 %0, %1;" : "=r"(r) : "f"(x));
    return r;
}

// ---------------- scatter: lvl_aggr[s] += h, lvl_aggr[t] += h ----------------
__global__ void k_scatter(const int* __restrict__ ep, int E)
{
    int idx = blockIdx.x * blockDim.x + threadIdx.x;
    int total = E * 32;
    if (idx >= total) return;
    int e = idx >> 5;
    int c4 = (idx & 31) * 4;
    float4 v = *(const float4*)(g_hpre + (size_t)e * CC + c4);
    float4 a = *(const float4*)(g_aff_a + c4);
    float4 d = *(const float4*)(g_aff_d + c4);
    v.x = fmaxf(fmaf(a.x, v.x, d.x), 0.f);
    v.y = fmaxf(fmaf(a.y, v.y, d.y), 0.f);
    v.z = fmaxf(fmaf(a.z, v.z, d.z), 0.f);
    v.w = fmaxf(fmaf(a.w, v.w, d.w), 0.f);
    int s = ep[e];
    int t = ep[E + e];
    float* ps = g_lvl + (size_t)s * CC + c4;
    float* pt = g_lvl + (size_t)t * CC + c4;
    asm volatile("red.global.add.v4.f32 [%0], {%1,%2,%3,%4};"
                 :: "l"(ps), "f"(v.x), "f"(v.y), "f"(v.z), "f"(v.w) : "memory");
    asm volatile("red.global.add.v4.f32 [%0], {%1,%2,%3,%4};"
                 :: "l"(pt), "f"(v.x), "f"(v.y), "f"(v.z), "f"(v.w) : "memory");
}

// ---------------- fused tf32 tensor-core GEMM + BN-stats epilogue ----------------
// Round-16 structure with a bigger warp tile to cut smem-crossbar traffic
// (the measured 84% L1 bottleneck):
//  * block tile 64x128, 128 threads = 4 warps (1m x 4n), warp tile 64x32
//    (4 m-tiles x 4 n-tiles of m16n8k8) -> 0.375 LDS words per accumulator
//    instead of 0.5 (25% less smem traffic).
//  * __launch_bounds__(128,4): 4 independent CTAs/SM at <=128 regs.
//  * grid mapping N-fast retained (A-panel L2 reuse).
//  * unroll 4 for both trip counts (body grew; keep window inside L0 I$).
// Per-element math identical to rounds 9..16 -> same rel_err.
// MODE 0: A = concat(node[s]+node[t], edge[row])     (K=256, gathers)
// MODE 1: A = (1+*eps)*A0[row] + A1[row]             (K=128)
// MODE 2: A = relu(aIn[k]*A0[row,k] + dIn[k])        (row stride K)
// MODE 3: A = (1+*eps)*edge[row] + node[s]+node[t]   (K=128, gathers)
#define BM 64
#define BN 128
#define BK 16
#define TPG 128

template<int MODE, int KV>
__global__ __launch_bounds__(TPG, 4) void k_gemm(
    const float* __restrict__ A0, const float* __restrict__ A1,
    const float* __restrict__ W,  const float* __restrict__ eps_ptr,
    const float* __restrict__ aIn, const float* __restrict__ dIn,
    const int* __restrict__ ep, int E,
    float* __restrict__ out, float* __restrict__ statSum, float* __restrict__ statSq,
    int M, int NC)
{
    __shared__ uint32_t As[2][BM][BK + 4];   // 10.2 KB
    __shared__ uint32_t Bs[2][BK][BN + 8];   // 17.4 KB
    __shared__ float ssum[BN];
    __shared__ float ssq[BN];

    const int tid    = threadIdx.x;
    const int warpId = tid >> 5;             // 0..3
    const int lane   = tid & 31;
    const int g      = lane >> 2;
    const int t      = lane & 3;
    const int n0w    = warpId * 32;          // 4 n-slots; all warps cover m=0..63
    const int m_blk  = blockIdx.y * BM;      // M on slow axis
    const int nb     = blockIdx.x * BN;      // N on fast axis (A-tile reuse in L2)

    // A-loader geometry: 128 threads cover 64x16 in two float4 each
    const int k4 = (tid & 3) * 4;            // 0,4,8,12
    int aRowL[2], aRowG[2], sIdx[2], tIdx[2];
#pragma unroll
    for (int j = 0; j < 2; j++) {
        aRowL[j] = (tid + j * 128) >> 2;     // 0..31, 32..63
        aRowG[j] = m_blk + aRowL[j];
        sIdx[j] = 0; tIdx[j] = 0;
        if constexpr (MODE == 0 || MODE == 3) {
            if (aRowG[j] < M) {
                sIdx[j] = ep[aRowG[j]];
                tIdx[j] = ep[E + aRowG[j]];
            }
        }
    }
    // B-loader geometry: 4 float4 per thread covering 16x128
    int bRowL[4], bColL[4];
#pragma unroll
    for (int j = 0; j < 4; j++) {
        int f = tid + j * 128;
        bRowL[j] = f >> 5;                   // 0..15
        bColL[j] = (f & 31) * 4;             // 0..124
    }

    float epsv = 0.f;
    if constexpr (MODE == 1 || MODE == 3) epsv = 1.f + __ldg(eps_ptr);

    float acc[4][4][4];                      // [mt][nt][c]
#pragma unroll
    for (int i = 0; i < 4; i++)
#pragma unroll
        for (int j = 0; j < 4; j++)
#pragma unroll
            for (int c = 0; c < 4; c++) acc[i][j][c] = 0.f;

    constexpr int nIter = KV / BK;           // 8 or 16, compile-time
    float4 aPre[2];
    float4 bPre[4];

    auto loadA1 = [&](int j, int gk) -> float4 {
        float4 av = make_float4(0.f, 0.f, 0.f, 0.f);
        if (aRowG[j] < M) {
            if constexpr (MODE == 0) {
                if (gk < 128) {
                    float4 x = *(const float4*)(A0 + (size_t)sIdx[j] * 128 + gk);
                    float4 y = *(const float4*)(A0 + (size_t)tIdx[j] * 128 + gk);
                    av.x = x.x + y.x; av.y = x.y + y.y;
                    av.z = x.z + y.z; av.w = x.w + y.w;
                } else {
                    av = *(const float4*)(A1 + (size_t)aRowG[j] * 128 + (gk - 128));
                }
            } else if constexpr (MODE == 1) {
                float4 x = *(const float4*)(A0 + (size_t)aRowG[j] * 128 + gk);
                float4 y = *(const float4*)(A1 + (size_t)aRowG[j] * 128 + gk);
                av.x = fmaf(epsv, x.x, y.x);
                av.y = fmaf(epsv, x.y, y.y);
                av.z = fmaf(epsv, x.z, y.z);
                av.w = fmaf(epsv, x.w, y.w);
            } else if constexpr (MODE == 2) {
                float4 x = *(const float4*)(A0 + (size_t)aRowG[j] * KV + gk);
                float4 a = *(const float4*)(aIn + gk);
                float4 d = *(const float4*)(dIn + gk);
                av.x = fmaxf(fmaf(a.x, x.x, d.x), 0.f);
                av.y = fmaxf(fmaf(a.y, x.y, d.y), 0.f);
                av.z = fmaxf(fmaf(a.z, x.z, d.z), 0.f);
                av.w = fmaxf(fmaf(a.w, x.w, d.w), 0.f);
            } else { // MODE 3
                float4 eV = *(const float4*)(A0 + (size_t)aRowG[j] * 128 + gk);
                float4 x = *(const float4*)(A1 + (size_t)sIdx[j] * 128 + gk);
                float4 y = *(const float4*)(A1 + (size_t)tIdx[j] * 128 + gk);
                av.x = fmaf(epsv, eV.x, x.x + y.x);
                av.y = fmaf(epsv, eV.y, x.y + y.y);
                av.z = fmaf(epsv, eV.z, x.z + y.z);
                av.w = fmaf(epsv, eV.w, x.w + y.w);
            }
        }
        return av;
    };
    auto loadTile = [&](int it) {
        int gk = it * BK + k4;
#pragma unroll
        for (int j = 0; j < 2; j++) aPre[j] = loadA1(j, gk);
#pragma unroll
        for (int j = 0; j < 4; j++)
            bPre[j] = *(const float4*)(W + (size_t)(it * BK + bRowL[j]) * NC + nb + bColL[j]);
    };
    auto storeTile = [&](int buf) {
#pragma unroll
        for (int j = 0; j < 2; j++)
            *(uint4*)&As[buf][aRowL[j]][k4] =
                make_uint4(f2tf32(aPre[j].x), f2tf32(aPre[j].y),
                           f2tf32(aPre[j].z), f2tf32(aPre[j].w));
#pragma unroll
        for (int j = 0; j < 4; j++)
            *(uint4*)&Bs[buf][bRowL[j]][bColL[j]] =
                make_uint4(f2tf32(bPre[j].x), f2tf32(bPre[j].y),
                           f2tf32(bPre[j].z), f2tf32(bPre[j].w));
    };
    auto iterBody = [&](int it) {
        const int buf = it & 1;
        if (it + 1 < nIter) loadTile(it + 1);   // overlap with MMAs below

#pragma unroll
        for (int ks = 0; ks < 2; ks++) {
            const int kb = ks * 8;
            uint32_t af[4][4];
            uint32_t bf[4][2];
#pragma unroll
            for (int mt = 0; mt < 4; mt++) {
                int r = mt * 16 + g;
                af[mt][0] = As[buf][r][kb + t];
                af[mt][1] = As[buf][r + 8][kb + t];
                af[mt][2] = As[buf][r][kb + t + 4];
                af[mt][3] = As[buf][r + 8][kb + t + 4];
            }
#pragma unroll
            for (int nt = 0; nt < 4; nt++) {
                int c = n0w + nt * 8 + g;
                bf[nt][0] = Bs[buf][kb + t][c];
                bf[nt][1] = Bs[buf][kb + t + 4][c];
            }
#pragma unroll
            for (int mt = 0; mt < 4; mt++)
#pragma unroll
                for (int nt = 0; nt < 4; nt++) {
                    asm volatile(
                        "mma.sync.aligned.m16n8k8.row.col.f32.tf32.tf32.f32 "
                        "{%0,%1,%2,%3}, {%4,%5,%6,%7}, {%8,%9}, {%0,%1,%2,%3};"
                        : "+f"(acc[mt][nt][0]), "+f"(acc[mt][nt][1]),
                          "+f"(acc[mt][nt][2]), "+f"(acc[mt][nt][3])
                        : "r"(af[mt][0]), "r"(af[mt][1]), "r"(af[mt][2]), "r"(af[mt][3]),
                          "r"(bf[nt][0]), "r"(bf[nt][1]));
                }
        }

        if (it + 1 < nIter) storeTile(buf ^ 1);
        __syncthreads();
    };

    loadTile(0);
    storeTile(0);
    __syncthreads();

#pragma unroll 4
    for (int it = 0; it < nIter; it++) iterBody(it);

    // ---- epilogue: per-column stats (shfl-reduced) + store ----
    for (int i = tid; i < BN; i += TPG) { ssum[i] = 0.f; ssq[i] = 0.f; }
    __syncthreads();

#pragma unroll
    for (int nt = 0; nt < 4; nt++) {
        float se = 0.f, qe = 0.f, so = 0.f, qo = 0.f;
#pragma unroll
        for (int mt = 0; mt < 4; mt++) {
            float c0 = acc[mt][nt][0], c1 = acc[mt][nt][1];
            float c2 = acc[mt][nt][2], c3 = acc[mt][nt][3];
            se += c0 + c2; qe += c0 * c0 + c2 * c2;
            so += c1 + c3; qo += c1 * c1 + c3 * c3;
        }
        // butterfly-sum across the 8 g-lanes (same t, lanes stride 4)
#pragma unroll
        for (int off = 16; off >= 4; off >>= 1) {
            se += __shfl_xor_sync(0xffffffffu, se, off);
            qe += __shfl_xor_sync(0xffffffffu, qe, off);
            so += __shfl_xor_sync(0xffffffffu, so, off);
            qo += __shfl_xor_sync(0xffffffffu, qo, off);
        }
        if (g == 0) {
            int ce = n0w + nt * 8 + 2 * t;
            atomicAdd(&ssum[ce], se);     atomicAdd(&ssq[ce], qe);
            atomicAdd(&ssum[ce + 1], so); atomicAdd(&ssq[ce + 1], qo);
        }
    }

#pragma unroll
    for (int mt = 0; mt < 4; mt++) {
        int r0 = m_blk + mt * 16 + g;
        int r1 = r0 + 8;
#pragma unroll
        for (int nt = 0; nt < 4; nt++) {
            int ce = n0w + nt * 8 + 2 * t;
            if (r0 < M) {
                float2 v = make_float2(acc[mt][nt][0], acc[mt][nt][1]);
                *(float2*)(out + (size_t)r0 * NC + nb + ce) = v;
            }
            if (r1 < M) {
                float2 v = make_float2(acc[mt][nt][2], acc[mt][nt][3]);
                *(float2*)(out + (size_t)r1 * NC + nb + ce) = v;
            }
        }
    }

    __syncthreads();
    for (int i = tid; i < BN; i += TPG) {
        atomicAdd(&statSum[nb + i], ssum[i]);
        atomicAdd(&statSq[nb + i], ssq[i]);
    }
}

// ---------------- finalize BN stats -> affine (a, d) ----------------
__global__ void k_finalize(const float* __restrict__ sums, const float* __restrict__ sqs,
                           const float* __restrict__ g, const float* __restrict__ b,
                           float* __restrict__ aA, float* __restrict__ aD,
                           int ncols, float invM)
{
    int i = blockIdx.x * blockDim.x + threadIdx.x;
    if (i >= ncols) return;
    float mu = sums[i] * invM;
    float var = sqs[i] * invM - mu * mu;
    float rs = rsqrtf(var + 1e-5f);
    float a = g[i] * rs;
    aA[i] = a;
    aD[i] = fmaf(-mu, a, b[i]);
}

// ---------------- final normalize + ReLU -> d_out ----------------
__global__ void k_norm(const float* __restrict__ in,
                       const float* __restrict__ aA, const float* __restrict__ aD,
                       float* __restrict__ out, int M)
{
    int idx = blockIdx.x * blockDim.x + threadIdx.x;
    int total = M * 32;
    if (idx >= total) return;
    int c4 = (idx & 31) * 4;
    float4 v = ((const float4*)in)[idx];
    float4 a = *(const float4*)(aA + c4);
    float4 d = *(const float4*)(aD + c4);
    v.x = fmaxf(fmaf(a.x, v.x, d.x), 0.f);
    v.y = fmaxf(fmaf(a.y, v.y, d.y), 0.f);
    v.z = fmaxf(fmaf(a.z, v.z, d.z), 0.f);
    v.w = fmaxf(fmaf(a.w, v.w, d.w), 0.f);
    ((float4*)out)[idx] = v;
}

// ---------------- host launch ----------------
extern "C" void kernel_launch(void* const* d_in, const int* in_sizes, int n_in,
                              void* d_out, int out_size)
{
    const float* node   = (const float*)d_in[0];
    const float* edge   = (const float*)d_in[1];
    const int*   ep     = (const int*)  d_in[2];
    const float* W_lvl1 = (const float*)d_in[3];
    const float* gl1    = (const float*)d_in[4];
    const float* bl1    = (const float*)d_in[5];
    const float* W_n1   = (const float*)d_in[6];
    const float* gn1    = (const float*)d_in[7];
    const float* bn1    = (const float*)d_in[8];
    const float* W_n2   = (const float*)d_in[9];
    const float* gn2    = (const float*)d_in[10];
    const float* bn2    = (const float*)d_in[11];
    const float* W_e1   = (const float*)d_in[12];
    const float* ge1    = (const float*)d_in[13];
    const float* be1    = (const float*)d_in[14];
    const float* W_e2   = (const float*)d_in[15];
    const float* ge2    = (const float*)d_in[16];
    const float* be2    = (const float*)d_in[17];
    const float* eps1   = (const float*)d_in[18];
    const float* eps2   = (const float*)d_in[19];
    float* outp = (float*)d_out;

    const int Cc = in_sizes[4];                  // 128
    const int Nn = in_sizes[0] / Cc;
    const int Ee = in_sizes[1] / Cc;

    float *hpre, *epre, *hidden, *hidden_n, *lvl, *outpre_n, *ssum, *ssq, *affA, *affD;
    cudaGetSymbolAddress((void**)&hpre,     g_hpre);
    cudaGetSymbolAddress((void**)&epre,     g_epre);
    cudaGetSymbolAddress((void**)&hidden,   g_hidden);
    cudaGetSymbolAddress((void**)&hidden_n, g_hidden_n);
    cudaGetSymbolAddress((void**)&lvl,      g_lvl);
    cudaGetSymbolAddress((void**)&outpre_n, g_outpre_n);
    cudaGetSymbolAddress((void**)&ssum,     g_stat_sum);
    cudaGetSymbolAddress((void**)&ssq,      g_stat_sq);
    cudaGetSymbolAddress((void**)&affA,     g_aff_a);
    cudaGetSymbolAddress((void**)&affD,     g_aff_d);

    static bool initDone = false;
    static cudaStream_t s1 = nullptr;
    static cudaEvent_t evFork = nullptr, evJoin = nullptr;
    if (!initDone) {
        cudaStreamCreateWithFlags(&s1, cudaStreamNonBlocking);
        cudaEventCreateWithFlags(&evFork, cudaEventDisableTiming);
        cudaEventCreateWithFlags(&evJoin, cudaEventDisableTiming);
        initDone = true;
    }

    cudaMemsetAsync(lvl,  0, (size_t)Nn * Cc * sizeof(float), 0);
    cudaMemsetAsync(ssum, 0, 5 * 256 * sizeof(float), 0);
    cudaMemsetAsync(ssq,  0, 5 * 256 * sizeof(float), 0);

    const int TPB = 256;
    const int eThreads = Ee * 32;
    const int nThreads = Nn * 32;
    const int gxE = (Ee + BM - 1) / BM;
    const int gxN = (Nn + BM - 1) / BM;

    // fork: edge chain on s1, node chain on stream 0
    cudaEventRecord(evFork, 0);
    cudaStreamWaitEvent(s1, evFork, 0);

    // ===== stream 0: lvl1 -> scatter -> node MLP =====
    // grid = (N-slabs, M-tiles): N fast so consecutive blocks reuse A rows
    k_gemm<0, 256><<<dim3(1, gxE), TPG, 0, 0>>>(node, edge, W_lvl1, nullptr, nullptr, nullptr,
                                                ep, Ee,
                                                hpre, ssum + 0, ssq + 0, Ee, 128);
    k_finalize<<<1, 256, 0, 0>>>(ssum + 0, ssq + 0, gl1, bl1, affA + 0, affD + 0,
                                 128, 1.f / (float)Ee);
    k_scatter<<<(eThreads + TPB - 1) / TPB, TPB, 0, 0>>>(ep, Ee);

    k_gemm<1, 128><<<dim3(2, gxN), TPG, 0, 0>>>(node, lvl, W_n1, eps1, nullptr, nullptr,
                                                nullptr, 0,
                                                hidden_n, ssum + 256, ssq + 256, Nn, 256);
    k_finalize<<<1, 256, 0, 0>>>(ssum + 256, ssq + 256, gn1, bn1, affA + 256, affD + 256,
                                 256, 1.f / (float)Nn);
    k_gemm<2, 256><<<dim3(1, gxN), TPG, 0, 0>>>(hidden_n, nullptr, W_n2, nullptr,
                                                affA + 256, affD + 256, nullptr, 0,
                                                outpre_n, ssum + 512, ssq + 512, Nn, 128);
    k_finalize<<<1, 256, 0, 0>>>(ssum + 512, ssq + 512, gn2, bn2, affA + 512, affD + 512,
                                 128, 1.f / (float)Nn);
    k_norm<<<(nThreads + TPB - 1) / TPB, TPB, 0, 0>>>(outpre_n, affA + 512, affD + 512,
                                                      outp, Nn);

    // ===== stream s1: edge MLP =====
    k_gemm<3, 128><<<dim3(2, gxE), TPG, 0, s1>>>(edge, node, W_e1, eps2, nullptr, nullptr,
                                                 ep, Ee,
                                                 hidden, ssum + 768, ssq + 768, Ee, 256);
    k_finalize<<<1, 256, 0, s1>>>(ssum + 768, ssq + 768, ge1, be1, affA + 768, affD + 768,
                                  256, 1.f / (float)Ee);
    k_gemm<2, 256><<<dim3(1, gxE), TPG, 0, s1>>>(hidden, nullptr, W_e2, nullptr,
                                                 affA + 768, affD + 768, nullptr, 0,
                                                 epre, ssum + 1024, ssq + 1024, Ee, 128);
    k_finalize<<<1, 256, 0, s1>>>(ssum + 1024, ssq + 1024, ge2, be2, affA + 1024, affD + 1024,
                                  128, 1.f / (float)Ee);
    k_norm<<<(eThreads + TPB - 1) / TPB, TPB, 0, s1>>>(epre, affA + 1024, affD + 1024,
                                                       outp + (size_t)Nn * Cc, Ee);

    // join
    cudaEventRecord(evJoin, s1);
    cudaStreamWaitEvent(0, evJoin, 0);
}